// round 2
// baseline (speedup 1.0000x reference)
#include <cuda_runtime.h>
#include <cstdint>

#define B 8
#define K 19
#define C 512
#define S 16384

// Scratch: unnormalized exp(aux - rowmax), plus per-row 1/sum.
__device__ float g_probs[B * K * S];
__device__ float g_invsum[B * K];

// ---------------------------------------------------------------------------
// Kernel 1: per-(b,k) row: rowmax, e = exp(x - max) -> g_probs, 1/sum(e).
// ---------------------------------------------------------------------------
__global__ void __launch_bounds__(256) softmax_stats_kernel(const float* __restrict__ aux) {
    const int row = blockIdx.x;                       // 0..151  (= b*19 + k)
    const float4* __restrict__ src = (const float4*)(aux + (size_t)row * S);
    float4* __restrict__ dst = (float4*)(g_probs + (size_t)row * S);
    const int tid = threadIdx.x;
    __shared__ float sred[32];
    __shared__ float smax;

    // phase 1: row max
    float m = -1e30f;
    #pragma unroll 4
    for (int i = tid; i < S / 4; i += 256) {
        float4 v = src[i];
        m = fmaxf(m, fmaxf(fmaxf(v.x, v.y), fmaxf(v.z, v.w)));
    }
    #pragma unroll
    for (int o = 16; o; o >>= 1) m = fmaxf(m, __shfl_xor_sync(0xffffffffu, m, o));
    if ((tid & 31) == 0) sred[tid >> 5] = m;
    __syncthreads();
    if (tid == 0) {
        float v = sred[0];
        #pragma unroll
        for (int w = 1; w < 8; ++w) v = fmaxf(v, sred[w]);
        smax = v;
    }
    __syncthreads();
    const float mx = smax;

    // phase 2: e = exp(x - mx), write unnormalized, accumulate sum
    float sum = 0.f;
    #pragma unroll 4
    for (int i = tid; i < S / 4; i += 256) {
        float4 v = src[i];
        float4 e;
        e.x = __expf(v.x - mx);
        e.y = __expf(v.y - mx);
        e.z = __expf(v.z - mx);
        e.w = __expf(v.w - mx);
        dst[i] = e;
        sum += (e.x + e.y) + (e.z + e.w);
    }
    #pragma unroll
    for (int o = 16; o; o >>= 1) sum += __shfl_xor_sync(0xffffffffu, sum, o);
    if ((tid & 31) == 0) sred[tid >> 5] = sum;
    __syncthreads();
    if (tid == 0) {
        float t = 0.f;
        #pragma unroll
        for (int w = 0; w < 8; ++w) t += sred[w];
        g_invsum[row] = 1.0f / t;
    }
}

// ---------------------------------------------------------------------------
// Kernel 2: ctx[b,k,c] = invsum[b,k] * sum_s e[b,k,s] * feats[b,c,s]
// 256 threads = 8 warps. Warp owns 2 channels; lanes split s (coalesced
// float4 loads). Register tile: 19 k x 2 c f32x2 accumulators = 76 regs,
// __launch_bounds__(256,2) forces <=128 regs -> 2 blocks/SM, 16 warps/SM.
// Grid (C/16, B) = 256 blocks -> single full wave at occ 2.
// ---------------------------------------------------------------------------
__device__ __forceinline__ void fma2(unsigned long long& acc,
                                     unsigned long long a,
                                     unsigned long long b) {
    asm("fma.rn.f32x2 %0, %1, %2, %3;" : "=l"(acc) : "l"(a), "l"(b), "l"(acc));
}

__global__ void __launch_bounds__(256, 2) gather_kernel(const float* __restrict__ feats,
                                                        float* __restrict__ out) {
    const int b    = blockIdx.y;
    const int warp = threadIdx.x >> 5;
    const int lane = threadIdx.x & 31;
    const int c_base = blockIdx.x * 16 + warp * 2;

    const ulonglong2* __restrict__ p0 =
        (const ulonglong2*)(g_probs + (size_t)b * K * S);
    const ulonglong2* __restrict__ f0 =
        (const ulonglong2*)(feats + (size_t)(b * C + c_base) * S);
    const int frow = S / 4;  // row stride in float4 units

    unsigned long long acc[K][2];
    #pragma unroll
    for (int k = 0; k < K; ++k) {
        acc[k][0] = 0ULL;
        acc[k][1] = 0ULL;
    }

    #pragma unroll 1
    for (int i = 0; i < S / 4 / 32; ++i) {  // 128 iterations
        const int idx = i * 32 + lane;
        ulonglong2 fv0 = f0[0 * frow + idx];
        ulonglong2 fv1 = f0[1 * frow + idx];
        #pragma unroll
        for (int k = 0; k < K; ++k) {
            ulonglong2 pv = p0[k * frow + idx];
            fma2(acc[k][0], pv.x, fv0.x);
            fma2(acc[k][1], pv.x, fv1.x);
            fma2(acc[k][0], pv.y, fv0.y);
            fma2(acc[k][1], pv.y, fv1.y);
        }
    }

    // Epilogue: pair-add, warp butterfly reduce, scale by invsum, store.
    #pragma unroll
    for (int k = 0; k < K; ++k) {
        const float inv = g_invsum[b * K + k];
        #pragma unroll
        for (int j = 0; j < 2; ++j) {
            float2 v = *(float2*)&acc[k][j];
            float s = v.x + v.y;
            s += __shfl_xor_sync(0xffffffffu, s, 16);
            s += __shfl_xor_sync(0xffffffffu, s, 8);
            s += __shfl_xor_sync(0xffffffffu, s, 4);
            s += __shfl_xor_sync(0xffffffffu, s, 2);
            s += __shfl_xor_sync(0xffffffffu, s, 1);
            if (lane == ((k * 2 + j) & 31))
                out[(size_t)(b * C + c_base + j) * K + k] = s * inv;
        }
    }
}

// ---------------------------------------------------------------------------
extern "C" void kernel_launch(void* const* d_in, const int* in_sizes, int n_in,
                              void* d_out, int out_size) {
    const float* feats = (const float*)d_in[0];  // [8,512,128,128]
    const float* aux   = (const float*)d_in[1];  // [8,19,128,128]
    float* out = (float*)d_out;                  // [8,512,19,1]

    softmax_stats_kernel<<<B * K, 256>>>(aux);
    dim3 grid(C / 16, B);
    gather_kernel<<<grid, 256>>>(feats, out);
}

// round 3
// speedup vs baseline: 2.0933x; 2.0933x over previous
#include <cuda_runtime.h>
#include <cstdint>

#define B 8
#define K 19
#define C 512
#define S 16384

#define CT     32            // channels per block
#define CHUNK  256           // s-floats per pipeline stage
#define STAGES 3
#define NCHUNK (S / CHUNK)   // 64
#define FEAT_FLOATS (CT * CHUNK)          // 8192
#define PROB_FLOATS (K * CHUNK)           // 4864
#define STAGE_FLOATS (FEAT_FLOATS + PROB_FLOATS)   // 13056 (52224 B)
#define SMEM_BYTES (STAGES * STAGE_FLOATS * 4)     // 156672
#define FEAT_TILES (FEAT_FLOATS / 4)      // 2048 16B tiles
#define ALL_TILES  (STAGE_FLOATS / 4)     // 3264 16B tiles

// Scratch: unnormalized exp(aux - rowmax), plus per-row 1/sum.
__device__ float g_probs[B * K * S];
__device__ float g_invsum[B * K];

// ---------------------------------------------------------------------------
// Kernel 1: per-(b,k) row: rowmax, e = exp(x - max) -> g_probs, 1/sum(e).
// ---------------------------------------------------------------------------
__global__ void __launch_bounds__(256) softmax_stats_kernel(const float* __restrict__ aux) {
    const int row = blockIdx.x;                       // 0..151  (= b*19 + k)
    const float4* __restrict__ src = (const float4*)(aux + (size_t)row * S);
    float4* __restrict__ dst = (float4*)(g_probs + (size_t)row * S);
    const int tid = threadIdx.x;
    __shared__ float sred[32];
    __shared__ float smax;

    float m = -1e30f;
    #pragma unroll 4
    for (int i = tid; i < S / 4; i += 256) {
        float4 v = src[i];
        m = fmaxf(m, fmaxf(fmaxf(v.x, v.y), fmaxf(v.z, v.w)));
    }
    #pragma unroll
    for (int o = 16; o; o >>= 1) m = fmaxf(m, __shfl_xor_sync(0xffffffffu, m, o));
    if ((tid & 31) == 0) sred[tid >> 5] = m;
    __syncthreads();
    if (tid == 0) {
        float v = sred[0];
        #pragma unroll
        for (int w = 1; w < 8; ++w) v = fmaxf(v, sred[w]);
        smax = v;
    }
    __syncthreads();
    const float mx = smax;

    float sum = 0.f;
    #pragma unroll 4
    for (int i = tid; i < S / 4; i += 256) {
        float4 v = src[i];
        float4 e;
        e.x = __expf(v.x - mx);
        e.y = __expf(v.y - mx);
        e.z = __expf(v.z - mx);
        e.w = __expf(v.w - mx);
        dst[i] = e;
        sum += (e.x + e.y) + (e.z + e.w);
    }
    #pragma unroll
    for (int o = 16; o; o >>= 1) sum += __shfl_xor_sync(0xffffffffu, sum, o);
    if ((tid & 31) == 0) sred[tid >> 5] = sum;
    __syncthreads();
    if (tid == 0) {
        float t = 0.f;
        #pragma unroll
        for (int w = 0; w < 8; ++w) t += sred[w];
        g_invsum[row] = 1.0f / t;
    }
}

// ---------------------------------------------------------------------------
// Kernel 2: ctx[b,k,c] = invsum[b,k] * sum_s e[b,k,s] * feats[b,c,s]
// cp.async 3-stage pipeline: each chunk stages feats[32c][256s] + probs[19k][256s]
// into smem; 8 warps compute R1-style register tiles (19k x 4c f32x2 acc)
// fed by LDS.128. DRAM latency hidden by async prefetch, not registers.
// ---------------------------------------------------------------------------
__device__ __forceinline__ void fma2(unsigned long long& acc,
                                     unsigned long long a,
                                     unsigned long long b) {
    asm("fma.rn.f32x2 %0, %1, %2, %3;" : "=l"(acc) : "l"(a), "l"(b), "l"(acc));
}

__global__ void __launch_bounds__(256, 1) gather_kernel(const float* __restrict__ feats,
                                                        float* __restrict__ out) {
    extern __shared__ float sm[];
    const int b    = blockIdx.y;
    const int tid  = threadIdx.x;
    const int warp = tid >> 5;
    const int lane = tid & 31;
    const int cbase = blockIdx.x * CT;

    const float* __restrict__ fg = feats + (size_t)(b * C + cbase) * S;
    const float* __restrict__ pg = g_probs + (size_t)b * K * S;

    // Stage filler: 3264 16B cp.async tiles (2048 feats + 1216 probs).
    auto fill = [&](int chunk, int stage) {
        unsigned sb = (unsigned)__cvta_generic_to_shared(sm + stage * STAGE_FLOATS);
        const int soff = chunk * CHUNK;
        #pragma unroll 1
        for (int t = tid; t < ALL_TILES; t += 256) {
            const float* src;
            unsigned dst;
            if (t < FEAT_TILES) {
                int row = t >> 6, col = (t & 63) << 2;
                src = fg + (size_t)row * S + soff + col;
                dst = sb + (unsigned)(row * CHUNK + col) * 4u;
            } else {
                int u = t - FEAT_TILES;
                int row = u >> 6, col = (u & 63) << 2;
                src = pg + (size_t)row * S + soff + col;
                dst = sb + (unsigned)(FEAT_FLOATS + row * CHUNK + col) * 4u;
            }
            asm volatile("cp.async.cg.shared.global [%0], [%1], 16;\n"
                         :: "r"(dst), "l"(src));
        }
    };

    unsigned long long acc[K][4];
    #pragma unroll
    for (int k = 0; k < K; ++k)
        #pragma unroll
        for (int j = 0; j < 4; ++j) acc[k][j] = 0ULL;

    // Prologue: prefetch first STAGES-1 chunks.
    #pragma unroll
    for (int p = 0; p < STAGES - 1; ++p) {
        fill(p, p);
        asm volatile("cp.async.commit_group;\n");
    }

    #pragma unroll 1
    for (int it = 0; it < NCHUNK; ++it) {
        asm volatile("cp.async.wait_group %0;\n" :: "n"(STAGES - 2));
        __syncthreads();   // chunk `it` visible to all; prev compute done before refill

        const int pre = it + STAGES - 1;
        if (pre < NCHUNK) fill(pre, pre % STAGES);
        asm volatile("cp.async.commit_group;\n");

        const float* sb = sm + (it % STAGES) * STAGE_FLOATS;
        #pragma unroll
        for (int step = 0; step < 2; ++step) {
            const int s0 = step * 128 + lane * 4;
            const ulonglong2 fv0 = *(const ulonglong2*)(sb + (warp * 4 + 0) * CHUNK + s0);
            const ulonglong2 fv1 = *(const ulonglong2*)(sb + (warp * 4 + 1) * CHUNK + s0);
            const ulonglong2 fv2 = *(const ulonglong2*)(sb + (warp * 4 + 2) * CHUNK + s0);
            const ulonglong2 fv3 = *(const ulonglong2*)(sb + (warp * 4 + 3) * CHUNK + s0);
            #pragma unroll
            for (int k = 0; k < K; ++k) {
                ulonglong2 pv = *(const ulonglong2*)(sb + FEAT_FLOATS + k * CHUNK + s0);
                fma2(acc[k][0], pv.x, fv0.x);
                fma2(acc[k][1], pv.x, fv1.x);
                fma2(acc[k][2], pv.x, fv2.x);
                fma2(acc[k][3], pv.x, fv3.x);
                fma2(acc[k][0], pv.y, fv0.y);
                fma2(acc[k][1], pv.y, fv1.y);
                fma2(acc[k][2], pv.y, fv2.y);
                fma2(acc[k][3], pv.y, fv3.y);
            }
        }
    }

    // Epilogue: pair-add, warp butterfly reduce, scale by invsum, store.
    #pragma unroll
    for (int k = 0; k < K; ++k) {
        const float inv = g_invsum[b * K + k];
        #pragma unroll
        for (int j = 0; j < 4; ++j) {
            float2 v = *(float2*)&acc[k][j];
            float s = v.x + v.y;
            s += __shfl_xor_sync(0xffffffffu, s, 16);
            s += __shfl_xor_sync(0xffffffffu, s, 8);
            s += __shfl_xor_sync(0xffffffffu, s, 4);
            s += __shfl_xor_sync(0xffffffffu, s, 2);
            s += __shfl_xor_sync(0xffffffffu, s, 1);
            if (lane == ((k * 4 + j) & 31))
                out[(size_t)(b * C + cbase + warp * 4 + j) * K + k] = s * inv;
        }
    }
}

// ---------------------------------------------------------------------------
extern "C" void kernel_launch(void* const* d_in, const int* in_sizes, int n_in,
                              void* d_out, int out_size) {
    const float* feats = (const float*)d_in[0];  // [8,512,128,128]
    const float* aux   = (const float*)d_in[1];  // [8,19,128,128]
    float* out = (float*)d_out;                  // [8,512,19,1]

    cudaFuncSetAttribute(gather_kernel,
                         cudaFuncAttributeMaxDynamicSharedMemorySize, SMEM_BYTES);

    softmax_stats_kernel<<<B * K, 256>>>(aux);
    dim3 grid(C / CT, B);
    gather_kernel<<<grid, 256, SMEM_BYTES>>>(feats, out);
}

// round 4
// speedup vs baseline: 2.2178x; 1.0595x over previous
#include <cuda_runtime.h>
#include <cstdint>

#define B 8
#define K 19
#define C 512
#define S 16384

#define CT     32                      // channels per block
#define CHUNK  512                     // s-floats per pipeline stage
#define STAGES 2
#define ZSPLIT 4                       // s-range split across blocks
#define CPB    (S / CHUNK / ZSPLIT)    // 8 chunks per block
#define FEAT_FLOATS (CT * CHUNK)       // 16384
#define PROB_FLOATS (K * CHUNK)        // 9728
#define STAGE_FLOATS (FEAT_FLOATS + PROB_FLOATS)   // 26112
#define STAGE_BYTES  (STAGE_FLOATS * 4)            // 104448
#define SMEM_BYTES   (STAGES * STAGE_BYTES)        // 208896

// Scratch
__device__ float g_probs[B * K * S];       // unnormalized exp(aux - rowmax)
__device__ float g_invsum[B * K];
__device__ float g_part[ZSPLIT][B * C * K];

// ---------------------------------------------------------------------------
// Kernel 1: per-(b,k) row: rowmax, e = exp(x - max) -> g_probs, 1/sum(e).
// ---------------------------------------------------------------------------
__global__ void __launch_bounds__(256) softmax_stats_kernel(const float* __restrict__ aux) {
    const int row = blockIdx.x;                       // 0..151
    const float4* __restrict__ src = (const float4*)(aux + (size_t)row * S);
    float4* __restrict__ dst = (float4*)(g_probs + (size_t)row * S);
    const int tid = threadIdx.x;
    __shared__ float sred[32];
    __shared__ float smax;

    float m = -1e30f;
    #pragma unroll 4
    for (int i = tid; i < S / 4; i += 256) {
        float4 v = src[i];
        m = fmaxf(m, fmaxf(fmaxf(v.x, v.y), fmaxf(v.z, v.w)));
    }
    #pragma unroll
    for (int o = 16; o; o >>= 1) m = fmaxf(m, __shfl_xor_sync(0xffffffffu, m, o));
    if ((tid & 31) == 0) sred[tid >> 5] = m;
    __syncthreads();
    if (tid == 0) {
        float v = sred[0];
        #pragma unroll
        for (int w = 1; w < 8; ++w) v = fmaxf(v, sred[w]);
        smax = v;
    }
    __syncthreads();
    const float mx = smax;

    float sum = 0.f;
    #pragma unroll 4
    for (int i = tid; i < S / 4; i += 256) {
        float4 v = src[i];
        float4 e;
        e.x = __expf(v.x - mx);
        e.y = __expf(v.y - mx);
        e.z = __expf(v.z - mx);
        e.w = __expf(v.w - mx);
        dst[i] = e;
        sum += (e.x + e.y) + (e.z + e.w);
    }
    #pragma unroll
    for (int o = 16; o; o >>= 1) sum += __shfl_xor_sync(0xffffffffu, sum, o);
    if ((tid & 31) == 0) sred[tid >> 5] = sum;
    __syncthreads();
    if (tid == 0) {
        float t = 0.f;
        #pragma unroll
        for (int w = 0; w < 8; ++w) t += sred[w];
        g_invsum[row] = 1.0f / t;
    }
}

// ---------------------------------------------------------------------------
// Kernel 2: partial ctx over this block's s-range.
// cp.async 2-stage pipeline, CHUNK=512. Fill is constant-stride per thread:
// thread handles tiles t = tid + j*256; row = t>>7 advances by 2 per j, so
// gmem src advances by 2*S*4 bytes and smem dst by 2*CHUNK*4 bytes. Pure
// cp.async [base + imm] — no per-tile address ALU.
// ---------------------------------------------------------------------------
__device__ __forceinline__ void fma2(unsigned long long& acc,
                                     unsigned long long a,
                                     unsigned long long b) {
    asm("fma.rn.f32x2 %0, %1, %2, %3;" : "=l"(acc) : "l"(a), "l"(b), "l"(acc));
}

__global__ void __launch_bounds__(256, 1) gather_kernel(const float* __restrict__ feats) {
    extern __shared__ float sm[];
    const int b    = blockIdx.y;
    const int z    = blockIdx.z;
    const int tid  = threadIdx.x;
    const int warp = tid >> 5;
    const int lane = tid & 31;
    const int cbase = blockIdx.x * CT;

    // Per-thread constant fill bases (gmem + smem)
    const char* fsrc = (const char*)(feats + (size_t)(b * C + cbase) * S + z * (S / ZSPLIT))
                       + (size_t)(tid >> 7) * (S * 4) + (tid & 127) * 16;
    const char* psrc = (const char*)(g_probs + (size_t)b * K * S + z * (S / ZSPLIT))
                       + (size_t)(tid >> 7) * (S * 4) + (tid & 127) * 16;
    unsigned sbase = (unsigned)__cvta_generic_to_shared(sm);
    const unsigned fdst = sbase + (unsigned)((tid >> 7) * (CHUNK * 4) + (tid & 127) * 16);
    const unsigned pdst = fdst + FEAT_FLOATS * 4;
    const bool p_last = (tid < 128);   // tile guard for j==9 of probs

    auto fill = [&](int chunk, int stage) {
        const char* fs = fsrc + chunk * (CHUNK * 4);
        const char* ps = psrc + chunk * (CHUNK * 4);
        const unsigned fd = fdst + stage * STAGE_BYTES;
        const unsigned pd = pdst + stage * STAGE_BYTES;
        #pragma unroll
        for (int j = 0; j < 16; ++j)
            asm volatile("cp.async.cg.shared.global [%0], [%1], 16;\n"
                         :: "r"(fd + j * (2 * CHUNK * 4)), "l"(fs + (size_t)j * (2 * S * 4)));
        #pragma unroll
        for (int j = 0; j < 9; ++j)
            asm volatile("cp.async.cg.shared.global [%0], [%1], 16;\n"
                         :: "r"(pd + j * (2 * CHUNK * 4)), "l"(ps + (size_t)j * (2 * S * 4)));
        if (p_last)
            asm volatile("cp.async.cg.shared.global [%0], [%1], 16;\n"
                         :: "r"(pd + 9 * (2 * CHUNK * 4)), "l"(ps + (size_t)9 * (2 * S * 4)));
    };

    unsigned long long acc[K][4];
    #pragma unroll
    for (int k = 0; k < K; ++k)
        #pragma unroll
        for (int j = 0; j < 4; ++j) acc[k][j] = 0ULL;

    fill(0, 0);
    asm volatile("cp.async.commit_group;\n");

    #pragma unroll 1
    for (int it = 0; it < CPB; ++it) {
        asm volatile("cp.async.wait_group 0;\n");
        __syncthreads();   // chunk `it` visible; stage (it+1)&1 free to refill

        if (it + 1 < CPB) fill(it + 1, (it + 1) & 1);
        asm volatile("cp.async.commit_group;\n");

        const float* sb = sm + (it & 1) * STAGE_FLOATS;
        #pragma unroll
        for (int step = 0; step < CHUNK / 128; ++step) {
            const int s0 = step * 128 + lane * 4;
            const ulonglong2 fv0 = *(const ulonglong2*)(sb + (warp * 4 + 0) * CHUNK + s0);
            const ulonglong2 fv1 = *(const ulonglong2*)(sb + (warp * 4 + 1) * CHUNK + s0);
            const ulonglong2 fv2 = *(const ulonglong2*)(sb + (warp * 4 + 2) * CHUNK + s0);
            const ulonglong2 fv3 = *(const ulonglong2*)(sb + (warp * 4 + 3) * CHUNK + s0);
            #pragma unroll
            for (int k = 0; k < K; ++k) {
                ulonglong2 pv = *(const ulonglong2*)(sb + FEAT_FLOATS + k * CHUNK + s0);
                fma2(acc[k][0], pv.x, fv0.x);
                fma2(acc[k][1], pv.x, fv1.x);
                fma2(acc[k][2], pv.x, fv2.x);
                fma2(acc[k][3], pv.x, fv3.x);
                fma2(acc[k][0], pv.y, fv0.y);
                fma2(acc[k][1], pv.y, fv1.y);
                fma2(acc[k][2], pv.y, fv2.y);
                fma2(acc[k][3], pv.y, fv3.y);
            }
        }
    }

    // Epilogue: pair-add, warp butterfly reduce, write PARTIAL (no invsum).
    #pragma unroll
    for (int k = 0; k < K; ++k) {
        #pragma unroll
        for (int j = 0; j < 4; ++j) {
            float2 v = *(float2*)&acc[k][j];
            float s = v.x + v.y;
            s += __shfl_xor_sync(0xffffffffu, s, 16);
            s += __shfl_xor_sync(0xffffffffu, s, 8);
            s += __shfl_xor_sync(0xffffffffu, s, 4);
            s += __shfl_xor_sync(0xffffffffu, s, 2);
            s += __shfl_xor_sync(0xffffffffu, s, 1);
            if (lane == ((k * 4 + j) & 31))
                g_part[z][(size_t)(b * C + cbase + warp * 4 + j) * K + k] = s;
        }
    }
}

// ---------------------------------------------------------------------------
// Kernel 3: sum z-partials, apply invsum, write final out[b][c][k].
// ---------------------------------------------------------------------------
__global__ void __launch_bounds__(256) reduce_kernel(float* __restrict__ out) {
    const int i = blockIdx.x * 256 + threadIdx.x;
    if (i >= B * C * K) return;
    float s = g_part[0][i] + g_part[1][i] + g_part[2][i] + g_part[3][i];
    const int k = i % K;
    const int b = i / (C * K);
    out[i] = s * g_invsum[b * K + k];
}

// ---------------------------------------------------------------------------
extern "C" void kernel_launch(void* const* d_in, const int* in_sizes, int n_in,
                              void* d_out, int out_size) {
    const float* feats = (const float*)d_in[0];  // [8,512,128,128]
    const float* aux   = (const float*)d_in[1];  // [8,19,128,128]
    float* out = (float*)d_out;                  // [8,512,19,1]

    cudaFuncSetAttribute(gather_kernel,
                         cudaFuncAttributeMaxDynamicSharedMemorySize, SMEM_BYTES);

    softmax_stats_kernel<<<B * K, 256>>>(aux);
    dim3 grid(C / CT, B, ZSPLIT);
    gather_kernel<<<grid, 256, SMEM_BYTES>>>(feats);
    reduce_kernel<<<(B * C * K + 255) / 256, 256>>>(out);
}